// round 14
// baseline (speedup 1.0000x reference)
#include <cuda_runtime.h>
#include <cuda_fp16.h>
#include <cstddef>

// Scratch (allocation-free rule: device globals)
__device__ __half   g_hn [2u * 256u * 4096u];   // groupnorm output, f16 [b][c][n]
__device__ __half   g_att[2u * 256u * 4096u];   // attention output, f16 [b][c][n]
__device__ __half   g_wq [768u * 256u];         // w_qkv f16
__device__ __half   g_wp [256u * 256u];         // w_proj f16
__device__ unsigned g_qbf[2u * 4u * 4096u * 32u];  // Q f16x2 [b,h][token][d/2] (pre-scaled)
__device__ unsigned g_kbf[2u * 4u * 4096u * 32u];  // K f16x2 [b,h][token][d/2]
__device__ unsigned g_vbf[2u * 4u * 64u * 2048u];  // V f16x2 [b,h][d][token/2]

// ---------------------------------------------------------------------------
// helpers
// ---------------------------------------------------------------------------
__device__ __forceinline__ unsigned packf16(float lo, float hi) {
    unsigned d; asm("cvt.rn.f16x2.f32 %0, %1, %2;" : "=r"(d) : "f"(hi), "f"(lo)); return d;
}
__device__ __forceinline__ unsigned ex2x2(unsigned x) {
    unsigned r; asm("ex2.approx.f16x2 %0, %1;" : "=r"(r) : "r"(x)); return r;
}
__device__ __forceinline__ unsigned hadd2(unsigned a, unsigned b) {
    unsigned r; asm("add.rn.f16x2 %0, %1, %2;" : "=r"(r) : "r"(a), "r"(b)); return r;
}
__device__ __forceinline__ float h2sum(unsigned v) {
    float a, b;
    asm("{\n\t.reg .f16 l, h;\n\tmov.b32 {l, h}, %2;\n\t"
        "cvt.f32.f16 %0, l;\n\tcvt.f32.f16 %1, h;\n\t}"
        : "=f"(a), "=f"(b) : "r"(v));
    return a + b;
}
__device__ __forceinline__ void mma16f(float* c, unsigned a0, unsigned a1, unsigned a2, unsigned a3,
                                       unsigned b0, unsigned b1) {
    asm volatile("mma.sync.aligned.m16n8k16.row.col.f32.f16.f16.f32 "
                 "{%0,%1,%2,%3}, {%4,%5,%6,%7}, {%8,%9}, {%0,%1,%2,%3};"
                 : "+f"(c[0]), "+f"(c[1]), "+f"(c[2]), "+f"(c[3])
                 : "r"(a0), "r"(a1), "r"(a2), "r"(a3), "r"(b0), "r"(b1));
}
__device__ __forceinline__ void mma16h(unsigned* c, unsigned a0, unsigned a1, unsigned a2,
                                       unsigned a3, unsigned b0, unsigned b1) {
    asm volatile("mma.sync.aligned.m16n8k16.row.col.f16.f16.f16.f16 "
                 "{%0,%1}, {%2,%3,%4,%5}, {%6,%7}, {%0,%1};"
                 : "+r"(c[0]), "+r"(c[1])
                 : "r"(a0), "r"(a1), "r"(a2), "r"(a3), "r"(b0), "r"(b1));
}
__device__ __forceinline__ void cpasync16(unsigned dst, const void* src) {
    asm volatile("cp.async.cg.shared.global [%0], [%1], 16;" :: "r"(dst), "l"(src));
}
__device__ __forceinline__ void ldsm4(unsigned& r0, unsigned& r1, unsigned& r2, unsigned& r3,
                                      unsigned addr) {
    asm volatile("ldmatrix.sync.aligned.m8n8.x4.shared.b16 {%0,%1,%2,%3}, [%4];"
                 : "=r"(r0), "=r"(r1), "=r"(r2), "=r"(r3) : "r"(addr));
}
__device__ __forceinline__ void ldsm4t(unsigned& r0, unsigned& r1, unsigned& r2, unsigned& r3,
                                       unsigned addr) {
    asm volatile("ldmatrix.sync.aligned.m8n8.x4.trans.shared.b16 {%0,%1,%2,%3}, [%4];"
                 : "=r"(r0), "=r"(r1), "=r"(r2), "=r"(r3) : "r"(addr));
}

// ---------------------------------------------------------------------------
// One-shot: weights -> f16.
// ---------------------------------------------------------------------------
__global__ void __launch_bounds__(256) round_w(const float* __restrict__ wq,
                                               const float* __restrict__ wp,
                                               __half* __restrict__ oq,
                                               __half* __restrict__ op) {
    int i = blockIdx.x * 256 + threadIdx.x;
    oq[i] = __float2half(wq[i]);
    if (i < 256 * 256) op[i] = __float2half(wp[i]);
}

// ---------------------------------------------------------------------------
// GroupNorm: f16 output [b][c][n].
// ---------------------------------------------------------------------------
__global__ void __launch_bounds__(1024) gn_kernel(const float* __restrict__ x,
                                                  const float* __restrict__ scale,
                                                  const float* __restrict__ bias,
                                                  __half* __restrict__ out) {
    const int b = blockIdx.x >> 5;
    const int g = blockIdx.x & 31;
    const float* xp = x   + ((size_t)b * 256 + g * 8) * 4096;
    __half*      op = out + ((size_t)b * 256 + g * 8) * 4096;
    const int tid = threadIdx.x;

    float s = 0.f, s2 = 0.f;
    for (int i = tid; i < 8 * 4096; i += 1024) {
        float v = xp[i];
        s += v; s2 += v * v;
    }
    __shared__ float rs[1024], rs2[1024];
    rs[tid] = s; rs2[tid] = s2;
    __syncthreads();
    for (int o = 512; o > 0; o >>= 1) {
        if (tid < o) { rs[tid] += rs[tid + o]; rs2[tid] += rs2[tid + o]; }
        __syncthreads();
    }
    const float mean = rs[0] * (1.f / 32768.f);
    const float var  = rs2[0] * (1.f / 32768.f) - mean * mean;
    const float inv  = rsqrtf(var + 1e-5f);

    for (int i = tid; i < 8 * 4096; i += 1024) {
        int c = g * 8 + (i >> 12);
        op[i] = __float2half((xp[i] - mean) * inv * scale[c] + bias[c]);
    }
}

// ---------------------------------------------------------------------------
// f16 GEMM: C[b,m,n] = sum_k A[m,k] * B[b,k,n], f32 accum.
// A [MT,256] f16 row-major -> non-trans ldmatrix (Q pattern).
// B [256,4096] f16 k-major -> ldmatrix.x4.trans gives col-major B frags.
// Block 64m x 128n, 8 warps (16m x 64n each), k-stage 32, cp.async x2 buf.
// A stage [64][40] f16 (pad), B stage [32][136] f16 (pad).
// ---------------------------------------------------------------------------
#define A_STG 5120            // bytes per A stage (64*40*2)
#define B_STG 8704            // bytes per B stage (32*136*2)
#define GEMM_SMEM_BYTES (2 * (A_STG + B_STG))   // 27648

template <int MT, bool EPI, bool QKVOUT>
__global__ void __launch_bounds__(256) gemm16(const __half* __restrict__ A,
                                              const __half* __restrict__ Bmat,
                                              float* __restrict__ C,
                                              const float* __restrict__ bias,
                                              const float* __restrict__ resid,
                                              unsigned* __restrict__ qbf,
                                              unsigned* __restrict__ kbf,
                                              unsigned* __restrict__ vbf) {
    const int K = 256, N = 4096;
    extern __shared__ char dsm[];
    const unsigned as_a = (unsigned)__cvta_generic_to_shared(dsm);
    const unsigned bs_a = as_a + 2 * A_STG;

    const int bn = blockIdx.x * 128, bm = blockIdx.y * 64, b = blockIdx.z;
    const __half* Bb = Bmat + (size_t)b * K * N;

    const int tid = threadIdx.x;
    const int w = tid >> 5, lane = tid & 31, g = lane >> 2, t = lane & 3;
    const int wm = (w >> 1) * 16, wn = (w & 1) * 64;

    // fragment smem byte offsets
    const unsigned aoff = (unsigned)(wm + (lane & 15)) * 80 + ((lane & 16));     // A: rows, +16B for k hi
    const unsigned boff = (unsigned)(lane & 15) * 272 + ((lane & 16));           // B: k-rows, +16B for n+8

#define G16_ISSUE(st, d)                                                               \
    {                                                                                  \
        {   /* A: 64 rows x 4 chunks = 256 */                                          \
            int m = tid >> 2, c = tid & 3;                                             \
            cpasync16(as_a + (d) * A_STG + m * 80 + c * 16,                            \
                      A + (size_t)(bm + m) * K + (st) * 32 + c * 8);                   \
        }                                                                              \
        _Pragma("unroll")                                                              \
        for (int p = 0; p < 2; p++) {   /* B: 32 k-rows x 16 chunks = 512 */           \
            int idx = tid + p * 256;                                                   \
            int k = idx >> 4, nc = idx & 15;                                           \
            cpasync16(bs_a + (d) * B_STG + k * 272 + nc * 16,                          \
                      Bb + (size_t)((st) * 32 + k) * N + bn + nc * 8);                 \
        }                                                                              \
        asm volatile("cp.async.commit_group;");                                        \
    }

    float acc[8][4];
#pragma unroll
    for (int nn = 0; nn < 8; nn++)
#pragma unroll
        for (int e = 0; e < 4; e++) acc[nn][e] = 0.f;

    G16_ISSUE(0, 0);

    for (int kc = 0; kc < 8; kc++) {
        asm volatile("cp.async.wait_group 0;");
        __syncthreads();
        if (kc < 7) G16_ISSUE(kc + 1, (kc + 1) & 1);

        const unsigned asb = as_a + (kc & 1) * A_STG;
        const unsigned bsb = bs_a + (kc & 1) * B_STG;
#pragma unroll
        for (int kk = 0; kk < 2; kk++) {
            unsigned a0, a1, a2, a3;
            ldsm4(a0, a1, a2, a3, asb + aoff + kk * 32);
#pragma unroll
            for (int j = 0; j < 4; j++) {
                unsigned b0, b1, b2, b3;
                ldsm4t(b0, b1, b2, b3, bsb + boff + kk * 16 * 272 + (wn + j * 16) * 2);
                mma16f(acc[2 * j],     a0, a1, a2, a3, b0, b1);
                mma16f(acc[2 * j + 1], a0, a1, a2, a3, b2, b3);
            }
        }
    }

    if (QKVOUT) {
        const int sel = blockIdx.y >> 2, hh = blockIdx.y & 3;
        if (sel < 2) {
            const float scl = (sel == 0) ? 0.125f * 1.4426950408889634f : 1.f;
            unsigned* outp = (sel == 0 ? qbf : kbf) + ((size_t)(b * 4 + hh) * 4096) * 32;
#pragma unroll
            for (int nn = 0; nn < 8; nn++) {
                float p0 = __shfl_xor_sync(0xffffffffu, acc[nn][0], 4);
                float p1 = __shfl_xor_sync(0xffffffffu, acc[nn][1], 4);
                float p2 = __shfl_xor_sync(0xffffffffu, acc[nn][2], 4);
                float p3 = __shfl_xor_sync(0xffffffffu, acc[nn][3], 4);
                if (!(g & 1)) {
                    int tok = bn + wn + nn * 8 + 2 * t;
                    int dpl = (wm + g) >> 1, dph = dpl + 4;
                    outp[(size_t)tok * 32 + dpl]       = packf16(acc[nn][0] * scl, p0 * scl);
                    outp[(size_t)(tok + 1) * 32 + dpl] = packf16(acc[nn][1] * scl, p1 * scl);
                    outp[(size_t)tok * 32 + dph]       = packf16(acc[nn][2] * scl, p2 * scl);
                    outp[(size_t)(tok + 1) * 32 + dph] = packf16(acc[nn][3] * scl, p3 * scl);
                }
            }
        } else {
            unsigned* outp = vbf + (size_t)(b * 4 + hh) * 64 * 2048;
#pragma unroll
            for (int nn = 0; nn < 8; nn++) {
                int tokp = (bn + wn + nn * 8) / 2 + t;
                outp[(size_t)(wm + g) * 2048 + tokp]     = packf16(acc[nn][0], acc[nn][1]);
                outp[(size_t)(wm + g + 8) * 2048 + tokp] = packf16(acc[nn][2], acc[nn][3]);
            }
        }
        return;
    }

    float* Cb = C + (size_t)b * MT * N;
    const int m0 = bm + wm + g;
#pragma unroll
    for (int nn = 0; nn < 8; nn++) {
        int col = bn + wn + nn * 8 + 2 * t;
        float2 v0 = make_float2(acc[nn][0], acc[nn][1]);
        float2 v1 = make_float2(acc[nn][2], acc[nn][3]);
        if (EPI) {
            float bz0 = bias[m0], bz1 = bias[m0 + 8];
            const float* rb2 = resid + (size_t)b * MT * N;
            float2 r0 = *(const float2*)(rb2 + (size_t)m0 * N + col);
            float2 r1 = *(const float2*)(rb2 + (size_t)(m0 + 8) * N + col);
            v0.x += bz0 + r0.x; v0.y += bz0 + r0.y;
            v1.x += bz1 + r1.x; v1.y += bz1 + r1.y;
        }
        *(float2*)(Cb + (size_t)m0 * N + col) = v0;
        *(float2*)(Cb + (size_t)(m0 + 8) * N + col) = v1;
    }
}

// ---------------------------------------------------------------------------
// Flash attention (R13, unchanged except f16 output): f16-D S mma,
// deferred PV, 128 q-rows/block, two 64-key tiles per barrier region.
// ---------------------------------------------------------------------------
#define KV_STRIDE 36
#define KV_BUF    (64 * KV_STRIDE)
#define PAIR_BUF  (2 * KV_BUF)
#define ATTN_SMEM_BYTES ((128 * KV_STRIDE + 5 * PAIR_BUF) * 4)   // 110592

__global__ void __launch_bounds__(256, 2) attn_kernel(const unsigned* __restrict__ qbf,
                                                      const unsigned* __restrict__ kbf,
                                                      const unsigned* __restrict__ vbf,
                                                      __half* __restrict__ out) {
    extern __shared__ char smraw[];
    float* st = (float*)smraw;                    // [64][132] output staging (reuse)
    const unsigned sm_u32 = (unsigned)__cvta_generic_to_shared(smraw);
    const unsigned qs_a = sm_u32;
    const unsigned ks_a = sm_u32 + 128 * KV_STRIDE * 4;
    const unsigned vs_a = ks_a + 2 * PAIR_BUF * 4;

    const int b = blockIdx.z, h = blockIdx.y, qt = blockIdx.x;
    const unsigned* qb = qbf + ((size_t)(b * 4 + h) * 4096 + qt * 128) * 32;
    const unsigned* kb = kbf + ((size_t)(b * 4 + h) * 4096) * 32;
    const unsigned* vb = vbf + (size_t)(b * 4 + h) * 64 * 2048;

    const int tid = threadIdx.x;
    const int lane = tid & 31, g = lane >> 2, t = lane & 3;
    const int i0w = (tid >> 5) * 16;

    const unsigned qoff = (((unsigned)(i0w + (lane & 15)) * KV_STRIDE) << 2) + ((lane >> 4) << 4);
    const unsigned koff = ((((lane & 7) + ((lane & 16) >> 1)) * KV_STRIDE) << 2) + ((lane & 8) << 1);

#pragma unroll
    for (int p = 0; p < 4; p++) {
        int idx = tid + p * 256;
        int i = idx >> 3, c = idx & 7;
        cpasync16(qs_a + (i * KV_STRIDE + c * 4) * 4, qb + (size_t)i * 32 + c * 4);
    }

#define ISSUE_PAIR(kp, kbuf, vbuf)                                                   \
    {                                                                                \
        _Pragma("unroll")                                                            \
        for (int p = 0; p < 4; p++) {                                                \
            int idx = tid + p * 256;                                                 \
            int r = idx >> 3, c = idx & 7;                                           \
            cpasync16(ks_a + ((kbuf) * PAIR_BUF + r * KV_STRIDE + c * 4) * 4,        \
                      kb + ((size_t)((kp) * 128 + r)) * 32 + c * 4);                 \
        }                                                                            \
        _Pragma("unroll")                                                            \
        for (int p = 0; p < 4; p++) {                                                \
            int idx = tid + p * 256;                                                 \
            int half = idx >> 9, r = (idx >> 3) & 63, c = idx & 7;                   \
            cpasync16(vs_a + ((vbuf) * PAIR_BUF + half * KV_BUF + r * KV_STRIDE + c * 4) * 4, \
                      vb + (size_t)r * 2048 + ((kp) * 2 + half) * 32 + c * 4);       \
        }                                                                            \
        asm volatile("cp.async.commit_group;");                                      \
    }

    ISSUE_PAIR(0, 0, 0);

    float o[8][4];
    float l_lo = 0.f, l_hi = 0.f;
#pragma unroll
    for (int nn = 0; nn < 8; nn++)
#pragma unroll
        for (int e = 0; e < 4; e++) o[nn][e] = 0.f;

    unsigned pa[4][4];
    unsigned vprev = 0;

    for (int kp = 0; kp < 32; kp++) {
        asm volatile("cp.async.wait_group 0;");
        __syncthreads();
        if (kp < 31) ISSUE_PAIR(kp + 1, (kp + 1) & 1, (kp + 1) % 3);

        const unsigned kpb = ks_a + (kp & 1) * PAIR_BUF * 4;
        const unsigned vpb = vs_a + (kp % 3) * PAIR_BUF * 4;

#pragma unroll
        for (int hf = 0; hf < 2; hf++) {
            const unsigned ksb_a = kpb + hf * KV_BUF * 4;

            unsigned s16[8][2];
#pragma unroll
            for (int nn = 0; nn < 8; nn++) { s16[nn][0] = 0u; s16[nn][1] = 0u; }
#pragma unroll
            for (int kk = 0; kk < 4; kk++) {
                unsigned a0, a1, a2, a3;
                ldsm4(a0, a1, a2, a3, qs_a + qoff + kk * 32);
#pragma unroll
                for (int nn2 = 0; nn2 < 4; nn2++) {
                    unsigned k0, k1, k2, k3;
                    ldsm4(k0, k1, k2, k3, ksb_a + koff + nn2 * (16 * KV_STRIDE * 4) + kk * 32);
                    mma16h(s16[2 * nn2],     a0, a1, a2, a3, k0, k1);
                    mma16h(s16[2 * nn2 + 1], a0, a1, a2, a3, k2, k3);
                }
            }

            if (kp > 0 || hf > 0) {
#pragma unroll
                for (int kk = 0; kk < 4; kk++) {
#pragma unroll
                    for (int nn2 = 0; nn2 < 4; nn2++) {
                        unsigned v0, v1, v2, v3;
                        ldsm4(v0, v1, v2, v3, vprev + koff + nn2 * (16 * KV_STRIDE * 4) + kk * 32);
                        mma16f(o[2 * nn2],     pa[kk][0], pa[kk][1], pa[kk][2], pa[kk][3], v0, v1);
                        mma16f(o[2 * nn2 + 1], pa[kk][0], pa[kk][1], pa[kk][2], pa[kk][3], v2, v3);
                    }
                }
            }

#pragma unroll
            for (int kk = 0; kk < 4; kk++) {
                pa[kk][0] = ex2x2(s16[2 * kk][0]);
                pa[kk][1] = ex2x2(s16[2 * kk][1]);
                pa[kk][2] = ex2x2(s16[2 * kk + 1][0]);
                pa[kk][3] = ex2x2(s16[2 * kk + 1][1]);
            }
            unsigned sg = hadd2(hadd2(hadd2(pa[0][0], pa[0][2]), hadd2(pa[1][0], pa[1][2])),
                                hadd2(hadd2(pa[2][0], pa[2][2]), hadd2(pa[3][0], pa[3][2])));
            unsigned sh = hadd2(hadd2(hadd2(pa[0][1], pa[0][3]), hadd2(pa[1][1], pa[1][3])),
                                hadd2(hadd2(pa[2][1], pa[2][3]), hadd2(pa[3][1], pa[3][3])));
            l_lo += h2sum(sg);
            l_hi += h2sum(sh);

            vprev = vpb + hf * KV_BUF * 4;
        }
    }

#pragma unroll
    for (int kk = 0; kk < 4; kk++) {
#pragma unroll
        for (int nn2 = 0; nn2 < 4; nn2++) {
            unsigned v0, v1, v2, v3;
            ldsm4(v0, v1, v2, v3, vprev + koff + nn2 * (16 * KV_STRIDE * 4) + kk * 32);
            mma16f(o[2 * nn2],     pa[kk][0], pa[kk][1], pa[kk][2], pa[kk][3], v0, v1);
            mma16f(o[2 * nn2 + 1], pa[kk][0], pa[kk][1], pa[kk][2], pa[kk][3], v2, v3);
        }
    }

#pragma unroll
    for (int off = 1; off <= 2; off <<= 1) {
        l_lo += __shfl_xor_sync(0xffffffffu, l_lo, off);
        l_hi += __shfl_xor_sync(0xffffffffu, l_hi, off);
    }
    float inv_lo, inv_hi;
    asm("rcp.approx.f32 %0, %1;" : "=f"(inv_lo) : "f"(l_lo));
    asm("rcp.approx.f32 %0, %1;" : "=f"(inv_hi) : "f"(l_hi));
    __syncthreads();
#pragma unroll
    for (int nn = 0; nn < 8; nn++) {
        int d0 = nn * 8 + 2 * t;
        st[(d0)     * 132 + i0w + g]     = o[nn][0] * inv_lo;
        st[(d0 + 1) * 132 + i0w + g]     = o[nn][1] * inv_lo;
        st[(d0)     * 132 + i0w + g + 8] = o[nn][2] * inv_hi;
        st[(d0 + 1) * 132 + i0w + g + 8] = o[nn][3] * inv_hi;
    }
    __syncthreads();

    __half* ob = out + ((size_t)(b * 256 + h * 64)) * 4096 + qt * 128;
#pragma unroll
    for (int p = 0; p < 8; p++) {
        int idx = tid + p * 256;
        int d = idx >> 5, i4 = (idx & 31) * 4;
        float4 v = *(const float4*)(st + d * 132 + i4);
        uint2 hv = make_uint2(packf16(v.x, v.y), packf16(v.z, v.w));
        *(uint2*)(ob + (size_t)d * 4096 + i4) = hv;
    }
}

// ---------------------------------------------------------------------------
extern "C" void kernel_launch(void* const* d_in, const int* in_sizes, int n_in,
                              void* d_out, int out_size) {
    const float* x        = (const float*)d_in[0];
    const float* gn_scale = (const float*)d_in[1];
    const float* gn_bias  = (const float*)d_in[2];
    const float* w_qkv    = (const float*)d_in[3];
    const float* w_proj   = (const float*)d_in[4];
    const float* b_proj   = (const float*)d_in[5];
    float* out = (float*)d_out;

    __half *hn, *att, *wq, *wp;
    unsigned *qbf, *kbf, *vbf;
    cudaGetSymbolAddress((void**)&hn,  g_hn);
    cudaGetSymbolAddress((void**)&att, g_att);
    cudaGetSymbolAddress((void**)&wq,  g_wq);
    cudaGetSymbolAddress((void**)&wp,  g_wp);
    cudaGetSymbolAddress((void**)&qbf, g_qbf);
    cudaGetSymbolAddress((void**)&kbf, g_kbf);
    cudaGetSymbolAddress((void**)&vbf, g_vbf);

    // 0) weights -> f16
    round_w<<<768, 256>>>(w_qkv, w_proj, wq, wp);

    // 1) GroupNorm (f16 output)
    gn_kernel<<<64, 1024>>>(x, gn_scale, gn_bias, hn);

    // 2) QKV projection (f16 mma), epilogue emits f16x2 attention layouts
    cudaFuncSetAttribute(gemm16<768, false, true>,
                         cudaFuncAttributeMaxDynamicSharedMemorySize, GEMM_SMEM_BYTES);
    gemm16<768, false, true><<<dim3(32, 12, 2), 256, GEMM_SMEM_BYTES>>>(
        wq, hn, nullptr, nullptr, nullptr, qbf, kbf, vbf);

    // 3) Flash attention (unchanged; f16 output)
    cudaFuncSetAttribute(attn_kernel, cudaFuncAttributeMaxDynamicSharedMemorySize, ATTN_SMEM_BYTES);
    attn_kernel<<<dim3(32, 4, 2), 256, ATTN_SMEM_BYTES>>>(qbf, kbf, vbf, att);

    // 4) Output projection + bias + residual (f16 mma, f32 epilogue)
    cudaFuncSetAttribute(gemm16<256, true, false>,
                         cudaFuncAttributeMaxDynamicSharedMemorySize, GEMM_SMEM_BYTES);
    gemm16<256, true, false><<<dim3(32, 4, 2), 256, GEMM_SMEM_BYTES>>>(
        wp, att, out, b_proj, x, nullptr, nullptr, nullptr);
}

// round 15
// speedup vs baseline: 1.3889x; 1.3889x over previous
#include <cuda_runtime.h>
#include <cstddef>

// Scratch (allocation-free rule: device globals)
__device__ float    g_hn [2u * 256u * 4096u];   // groupnorm output (tf32-rounded)
__device__ float    g_att[2u * 256u * 4096u];   // attention output (tf32-rounded)
__device__ float    g_wq [768u * 256u];         // w_qkv tf32-rounded
__device__ float    g_wp [256u * 256u];         // w_proj tf32-rounded
__device__ unsigned g_qbf[2u * 4u * 4096u * 32u];  // Q f16x2 [b,h][token][d/2] (pre-scaled)
__device__ unsigned g_kbf[2u * 4u * 4096u * 32u];  // K f16x2 [b,h][token][d/2]
__device__ unsigned g_vbf[2u * 4u * 64u * 2048u];  // V f16x2 [b,h][d][token/2]

// ---------------------------------------------------------------------------
// helpers
// ---------------------------------------------------------------------------
__device__ __forceinline__ unsigned f2tf32(float x) {
    unsigned u; asm("cvt.rna.tf32.f32 %0, %1;" : "=r"(u) : "f"(x)); return u;
}
__device__ __forceinline__ float f2tf32f(float x) { return __uint_as_float(f2tf32(x)); }
__device__ __forceinline__ unsigned packf16(float lo, float hi) {
    unsigned d; asm("cvt.rn.f16x2.f32 %0, %1, %2;" : "=r"(d) : "f"(hi), "f"(lo)); return d;
}
__device__ __forceinline__ unsigned ex2x2(unsigned x) {
    unsigned r; asm("ex2.approx.f16x2 %0, %1;" : "=r"(r) : "r"(x)); return r;
}
__device__ __forceinline__ unsigned hadd2(unsigned a, unsigned b) {
    unsigned r; asm("add.rn.f16x2 %0, %1, %2;" : "=r"(r) : "r"(a), "r"(b)); return r;
}
__device__ __forceinline__ float h2sum(unsigned v) {
    float a, b;
    asm("{\n\t.reg .f16 l, h;\n\tmov.b32 {l, h}, %2;\n\t"
        "cvt.f32.f16 %0, l;\n\tcvt.f32.f16 %1, h;\n\t}"
        : "=f"(a), "=f"(b) : "r"(v));
    return a + b;
}
__device__ __forceinline__ void mma8(float* c, unsigned a0, unsigned a1, unsigned a2, unsigned a3,
                                     unsigned b0, unsigned b1) {
    asm volatile("mma.sync.aligned.m16n8k8.row.col.f32.tf32.tf32.f32 "
                 "{%0,%1,%2,%3}, {%4,%5,%6,%7}, {%8,%9}, {%0,%1,%2,%3};"
                 : "+f"(c[0]), "+f"(c[1]), "+f"(c[2]), "+f"(c[3])
                 : "r"(a0), "r"(a1), "r"(a2), "r"(a3), "r"(b0), "r"(b1));
}
__device__ __forceinline__ void mma16f(float* c, unsigned a0, unsigned a1, unsigned a2, unsigned a3,
                                       unsigned b0, unsigned b1) {
    asm volatile("mma.sync.aligned.m16n8k16.row.col.f32.f16.f16.f32 "
                 "{%0,%1,%2,%3}, {%4,%5,%6,%7}, {%8,%9}, {%0,%1,%2,%3};"
                 : "+f"(c[0]), "+f"(c[1]), "+f"(c[2]), "+f"(c[3])
                 : "r"(a0), "r"(a1), "r"(a2), "r"(a3), "r"(b0), "r"(b1));
}
__device__ __forceinline__ void mma16h(unsigned* c, unsigned a0, unsigned a1, unsigned a2,
                                       unsigned a3, unsigned b0, unsigned b1) {
    asm volatile("mma.sync.aligned.m16n8k16.row.col.f16.f16.f16.f16 "
                 "{%0,%1}, {%2,%3,%4,%5}, {%6,%7}, {%0,%1};"
                 : "+r"(c[0]), "+r"(c[1])
                 : "r"(a0), "r"(a1), "r"(a2), "r"(a3), "r"(b0), "r"(b1));
}
__device__ __forceinline__ void cpasync16(unsigned dst, const void* src) {
    asm volatile("cp.async.cg.shared.global [%0], [%1], 16;" :: "r"(dst), "l"(src));
}
__device__ __forceinline__ void ldsm4(unsigned& r0, unsigned& r1, unsigned& r2, unsigned& r3,
                                      unsigned addr) {
    asm volatile("ldmatrix.sync.aligned.m8n8.x4.shared.b16 {%0,%1,%2,%3}, [%4];"
                 : "=r"(r0), "=r"(r1), "=r"(r2), "=r"(r3) : "r"(addr));
}

// ---------------------------------------------------------------------------
// One-shot: round weights to tf32 (rna) so GEMMs can cp.async them raw.
// ---------------------------------------------------------------------------
__global__ void __launch_bounds__(256) round_w(const float* __restrict__ wq,
                                               const float* __restrict__ wp,
                                               float* __restrict__ oq,
                                               float* __restrict__ op) {
    int i = blockIdx.x * 256 + threadIdx.x;
    oq[i] = f2tf32f(wq[i]);
    if (i < 256 * 256) op[i] = f2tf32f(wp[i]);
}

// ---------------------------------------------------------------------------
// GroupNorm, register-cached single-pass: each thread holds 8 float4 (one
// channel per chunk k: c = g*8 + k), warp-shuffle + 32-entry smem reduce.
// Output tf32-rounded. 64 blocks x 1024 threads.
// ---------------------------------------------------------------------------
__global__ void __launch_bounds__(1024) gn_kernel(const float* __restrict__ x,
                                                  const float* __restrict__ scale,
                                                  const float* __restrict__ bias,
                                                  float* __restrict__ out) {
    const int b = blockIdx.x >> 5;
    const int g = blockIdx.x & 31;
    const float4* xp4 = (const float4*)(x   + ((size_t)b * 256 + g * 8) * 4096);
    float4*       op4 = (float4*)      (out + ((size_t)b * 256 + g * 8) * 4096);
    const int tid = threadIdx.x;

    float4 v[8];
    float s = 0.f, s2 = 0.f;
#pragma unroll
    for (int k = 0; k < 8; k++) {
        v[k] = xp4[tid + k * 1024];
        s  += (v[k].x + v[k].y) + (v[k].z + v[k].w);
        s2 += (v[k].x * v[k].x + v[k].y * v[k].y) + (v[k].z * v[k].z + v[k].w * v[k].w);
    }
#pragma unroll
    for (int off = 16; off >= 1; off >>= 1) {
        s  += __shfl_xor_sync(0xffffffffu, s,  off);
        s2 += __shfl_xor_sync(0xffffffffu, s2, off);
    }
    __shared__ float rs[32], rs2[32], bc[2];
    if ((tid & 31) == 0) { rs[tid >> 5] = s; rs2[tid >> 5] = s2; }
    __syncthreads();
    if (tid < 32) {
        float a = rs[tid], a2 = rs2[tid];
#pragma unroll
        for (int off = 16; off >= 1; off >>= 1) {
            a  += __shfl_xor_sync(0xffffffffu, a,  off);
            a2 += __shfl_xor_sync(0xffffffffu, a2, off);
        }
        if (tid == 0) { bc[0] = a; bc[1] = a2; }
    }
    __syncthreads();
    const float mean = bc[0] * (1.f / 32768.f);
    const float var  = bc[1] * (1.f / 32768.f) - mean * mean;
    const float inv  = rsqrtf(var + 1e-5f);

#pragma unroll
    for (int k = 0; k < 8; k++) {
        const int c = g * 8 + k;
        const float a  = inv * scale[c];
        const float b2 = bias[c] - mean * a;
        float4 o;
        o.x = f2tf32f(v[k].x * a + b2);
        o.y = f2tf32f(v[k].y * a + b2);
        o.z = f2tf32f(v[k].z * a + b2);
        o.w = f2tf32f(v[k].w * a + b2);
        op4[tid + k * 1024] = o;
    }
}

// ---------------------------------------------------------------------------
// tf32 GEMM, cp.async double-buffered (R13, known good).
// ---------------------------------------------------------------------------
#define GEMM_SMEM_BYTES ((2 * 64 * 36 + 2 * 32 * 136) * 4)

template <int MT, bool EPI, bool QKVOUT>
__global__ void __launch_bounds__(256) gemm_mma(const float* __restrict__ A,
                                                const float* __restrict__ Bmat,
                                                float* __restrict__ C,
                                                const float* __restrict__ bias,
                                                const float* __restrict__ resid,
                                                unsigned* __restrict__ qbf,
                                                unsigned* __restrict__ kbf,
                                                unsigned* __restrict__ vbf) {
    const int K = 256, N = 4096;
    extern __shared__ float dsm[];
    const unsigned as_a = (unsigned)__cvta_generic_to_shared(dsm);
    const unsigned bs_a = as_a + 2 * 64 * 36 * 4;

    const int bn = blockIdx.x * 128, bm = blockIdx.y * 64, b = blockIdx.z;
    const float* Bb = Bmat + (size_t)b * K * N;

    const int tid = threadIdx.x;
    const int w = tid >> 5, lane = tid & 31, g = lane >> 2, t = lane & 3;
    const int wm = (w >> 1) * 16, wn = (w & 1) * 64;

#define G_ISSUE(st, d)                                                                 \
    {                                                                                  \
        _Pragma("unroll")                                                              \
        for (int p = 0; p < 2; p++) {                                                  \
            int idx = tid + p * 256;                                                   \
            int m = idx >> 3, kq = (idx & 7) * 4;                                      \
            cpasync16(as_a + ((d) * 2304 + m * 36 + kq) * 4,                           \
                      A + (size_t)(bm + m) * K + (st) * 32 + kq);                      \
        }                                                                              \
        _Pragma("unroll")                                                              \
        for (int p = 0; p < 4; p++) {                                                  \
            int idx = tid + p * 256;                                                   \
            int k = idx >> 5, nq = (idx & 31) * 4;                                     \
            cpasync16(bs_a + ((d) * 4352 + k * 136 + nq) * 4,                          \
                      Bb + (size_t)((st) * 32 + k) * N + bn + nq);                     \
        }                                                                              \
        asm volatile("cp.async.commit_group;");                                        \
    }

    float acc[8][4];
#pragma unroll
    for (int nn = 0; nn < 8; nn++)
#pragma unroll
        for (int e = 0; e < 4; e++) acc[nn][e] = 0.f;

    G_ISSUE(0, 0);

    for (int kc = 0; kc < 8; kc++) {
        asm volatile("cp.async.wait_group 0;");
        __syncthreads();
        if (kc < 7) G_ISSUE(kc + 1, (kc + 1) & 1);

        const float* as = dsm + (kc & 1) * 2304;
        const float* bs = dsm + 2 * 2304 + (kc & 1) * 4352;
#pragma unroll
        for (int kk = 0; kk < 4; kk++) {
            unsigned a0 = __float_as_uint(as[(wm + g)     * 36 + kk * 8 + t]);
            unsigned a1 = __float_as_uint(as[(wm + g + 8) * 36 + kk * 8 + t]);
            unsigned a2 = __float_as_uint(as[(wm + g)     * 36 + kk * 8 + t + 4]);
            unsigned a3 = __float_as_uint(as[(wm + g + 8) * 36 + kk * 8 + t + 4]);
#pragma unroll
            for (int nn = 0; nn < 8; nn++) {
                unsigned b0 = __float_as_uint(bs[(kk * 8 + t)     * 136 + wn + nn * 8 + g]);
                unsigned b1 = __float_as_uint(bs[(kk * 8 + t + 4) * 136 + wn + nn * 8 + g]);
                mma8(acc[nn], a0, a1, a2, a3, b0, b1);
            }
        }
    }

    if (QKVOUT) {
        const int sel = blockIdx.y >> 2, hh = blockIdx.y & 3;
        if (sel < 2) {
            const float scl = (sel == 0) ? 0.125f * 1.4426950408889634f : 1.f;
            unsigned* outp = (sel == 0 ? qbf : kbf) + ((size_t)(b * 4 + hh) * 4096) * 32;
#pragma unroll
            for (int nn = 0; nn < 8; nn++) {
                float p0 = __shfl_xor_sync(0xffffffffu, acc[nn][0], 4);
                float p1 = __shfl_xor_sync(0xffffffffu, acc[nn][1], 4);
                float p2 = __shfl_xor_sync(0xffffffffu, acc[nn][2], 4);
                float p3 = __shfl_xor_sync(0xffffffffu, acc[nn][3], 4);
                if (!(g & 1)) {
                    int tok = bn + wn + nn * 8 + 2 * t;
                    int dpl = (wm + g) >> 1, dph = dpl + 4;
                    outp[(size_t)tok * 32 + dpl]       = packf16(acc[nn][0] * scl, p0 * scl);
                    outp[(size_t)(tok + 1) * 32 + dpl] = packf16(acc[nn][1] * scl, p1 * scl);
                    outp[(size_t)tok * 32 + dph]       = packf16(acc[nn][2] * scl, p2 * scl);
                    outp[(size_t)(tok + 1) * 32 + dph] = packf16(acc[nn][3] * scl, p3 * scl);
                }
            }
        } else {
            unsigned* outp = vbf + (size_t)(b * 4 + hh) * 64 * 2048;
#pragma unroll
            for (int nn = 0; nn < 8; nn++) {
                int tokp = (bn + wn + nn * 8) / 2 + t;
                outp[(size_t)(wm + g) * 2048 + tokp]     = packf16(acc[nn][0], acc[nn][1]);
                outp[(size_t)(wm + g + 8) * 2048 + tokp] = packf16(acc[nn][2], acc[nn][3]);
            }
        }
        return;
    }

    float* Cb = C + (size_t)b * MT * N;
    const int m0 = bm + wm + g;
#pragma unroll
    for (int nn = 0; nn < 8; nn++) {
        int col = bn + wn + nn * 8 + 2 * t;
        float2 v0 = make_float2(acc[nn][0], acc[nn][1]);
        float2 v1 = make_float2(acc[nn][2], acc[nn][3]);
        if (EPI) {
            float bz0 = bias[m0], bz1 = bias[m0 + 8];
            const float* rb2 = resid + (size_t)b * MT * N;
            float2 r0 = *(const float2*)(rb2 + (size_t)m0 * N + col);
            float2 r1 = *(const float2*)(rb2 + (size_t)(m0 + 8) * N + col);
            v0.x += bz0 + r0.x; v0.y += bz0 + r0.y;
            v1.x += bz1 + r1.x; v1.y += bz1 + r1.y;
        }
        *(float2*)(Cb + (size_t)m0 * N + col) = v0;
        *(float2*)(Cb + (size_t)(m0 + 8) * N + col) = v1;
    }
}

// ---------------------------------------------------------------------------
// Flash attention (R13 verbatim): f16-D S mma, deferred PV, 128 q-rows/block,
// two 64-key tiles per barrier region. V ring 3 pairs, K ring 2.
// ---------------------------------------------------------------------------
#define KV_STRIDE 36
#define KV_BUF    (64 * KV_STRIDE)
#define PAIR_BUF  (2 * KV_BUF)
#define ATTN_SMEM_BYTES ((128 * KV_STRIDE + 5 * PAIR_BUF) * 4)   // 110592

__global__ void __launch_bounds__(256, 2) attn_kernel(const unsigned* __restrict__ qbf,
                                                      const unsigned* __restrict__ kbf,
                                                      const unsigned* __restrict__ vbf,
                                                      float* __restrict__ out) {
    extern __shared__ char smraw[];
    float* st = (float*)smraw;
    const unsigned sm_u32 = (unsigned)__cvta_generic_to_shared(smraw);
    const unsigned qs_a = sm_u32;
    const unsigned ks_a = sm_u32 + 128 * KV_STRIDE * 4;
    const unsigned vs_a = ks_a + 2 * PAIR_BUF * 4;

    const int b = blockIdx.z, h = blockIdx.y, qt = blockIdx.x;
    const unsigned* qb = qbf + ((size_t)(b * 4 + h) * 4096 + qt * 128) * 32;
    const unsigned* kb = kbf + ((size_t)(b * 4 + h) * 4096) * 32;
    const unsigned* vb = vbf + (size_t)(b * 4 + h) * 64 * 2048;

    const int tid = threadIdx.x;
    const int lane = tid & 31, g = lane >> 2, t = lane & 3;
    const int i0w = (tid >> 5) * 16;

    const unsigned qoff = (((unsigned)(i0w + (lane & 15)) * KV_STRIDE) << 2) + ((lane >> 4) << 4);
    const unsigned koff = ((((lane & 7) + ((lane & 16) >> 1)) * KV_STRIDE) << 2) + ((lane & 8) << 1);

#pragma unroll
    for (int p = 0; p < 4; p++) {
        int idx = tid + p * 256;
        int i = idx >> 3, c = idx & 7;
        cpasync16(qs_a + (i * KV_STRIDE + c * 4) * 4, qb + (size_t)i * 32 + c * 4);
    }

#define ISSUE_PAIR(kp, kbuf, vbuf)                                                   \
    {                                                                                \
        _Pragma("unroll")                                                            \
        for (int p = 0; p < 4; p++) {                                                \
            int idx = tid + p * 256;                                                 \
            int r = idx >> 3, c = idx & 7;                                           \
            cpasync16(ks_a + ((kbuf) * PAIR_BUF + r * KV_STRIDE + c * 4) * 4,        \
                      kb + ((size_t)((kp) * 128 + r)) * 32 + c * 4);                 \
        }                                                                            \
        _Pragma("unroll")                                                            \
        for (int p = 0; p < 4; p++) {                                                \
            int idx = tid + p * 256;                                                 \
            int half = idx >> 9, r = (idx >> 3) & 63, c = idx & 7;                   \
            cpasync16(vs_a + ((vbuf) * PAIR_BUF + half * KV_BUF + r * KV_STRIDE + c * 4) * 4, \
                      vb + (size_t)r * 2048 + ((kp) * 2 + half) * 32 + c * 4);       \
        }                                                                            \
        asm volatile("cp.async.commit_group;");                                      \
    }

    ISSUE_PAIR(0, 0, 0);

    float o[8][4];
    float l_lo = 0.f, l_hi = 0.f;
#pragma unroll
    for (int nn = 0; nn < 8; nn++)
#pragma unroll
        for (int e = 0; e < 4; e++) o[nn][e] = 0.f;

    unsigned pa[4][4];
    unsigned vprev = 0;

    for (int kp = 0; kp < 32; kp++) {
        asm volatile("cp.async.wait_group 0;");
        __syncthreads();
        if (kp < 31) ISSUE_PAIR(kp + 1, (kp + 1) & 1, (kp + 1) % 3);

        const unsigned kpb = ks_a + (kp & 1) * PAIR_BUF * 4;
        const unsigned vpb = vs_a + (kp % 3) * PAIR_BUF * 4;

#pragma unroll
        for (int hf = 0; hf < 2; hf++) {
            const unsigned ksb_a = kpb + hf * KV_BUF * 4;

            unsigned s16[8][2];
#pragma unroll
            for (int nn = 0; nn < 8; nn++) { s16[nn][0] = 0u; s16[nn][1] = 0u; }
#pragma unroll
            for (int kk = 0; kk < 4; kk++) {
                unsigned a0, a1, a2, a3;
                ldsm4(a0, a1, a2, a3, qs_a + qoff + kk * 32);
#pragma unroll
                for (int nn2 = 0; nn2 < 4; nn2++) {
                    unsigned k0, k1, k2, k3;
                    ldsm4(k0, k1, k2, k3, ksb_a + koff + nn2 * (16 * KV_STRIDE * 4) + kk * 32);
                    mma16h(s16[2 * nn2],     a0, a1, a2, a3, k0, k1);
                    mma16h(s16[2 * nn2 + 1], a0, a1, a2, a3, k2, k3);
                }
            }

            if (kp > 0 || hf > 0) {
#pragma unroll
                for (int kk = 0; kk < 4; kk++) {
#pragma unroll
                    for (int nn2 = 0; nn2 < 4; nn2++) {
                        unsigned v0, v1, v2, v3;
                        ldsm4(v0, v1, v2, v3, vprev + koff + nn2 * (16 * KV_STRIDE * 4) + kk * 32);
                        mma16f(o[2 * nn2],     pa[kk][0], pa[kk][1], pa[kk][2], pa[kk][3], v0, v1);
                        mma16f(o[2 * nn2 + 1], pa[kk][0], pa[kk][1], pa[kk][2], pa[kk][3], v2, v3);
                    }
                }
            }

#pragma unroll
            for (int kk = 0; kk < 4; kk++) {
                pa[kk][0] = ex2x2(s16[2 * kk][0]);
                pa[kk][1] = ex2x2(s16[2 * kk][1]);
                pa[kk][2] = ex2x2(s16[2 * kk + 1][0]);
                pa[kk][3] = ex2x2(s16[2 * kk + 1][1]);
            }
            unsigned sg = hadd2(hadd2(hadd2(pa[0][0], pa[0][2]), hadd2(pa[1][0], pa[1][2])),
                                hadd2(hadd2(pa[2][0], pa[2][2]), hadd2(pa[3][0], pa[3][2])));
            unsigned sh = hadd2(hadd2(hadd2(pa[0][1], pa[0][3]), hadd2(pa[1][1], pa[1][3])),
                                hadd2(hadd2(pa[2][1], pa[2][3]), hadd2(pa[3][1], pa[3][3])));
            l_lo += h2sum(sg);
            l_hi += h2sum(sh);

            vprev = vpb + hf * KV_BUF * 4;
        }
    }

#pragma unroll
    for (int kk = 0; kk < 4; kk++) {
#pragma unroll
        for (int nn2 = 0; nn2 < 4; nn2++) {
            unsigned v0, v1, v2, v3;
            ldsm4(v0, v1, v2, v3, vprev + koff + nn2 * (16 * KV_STRIDE * 4) + kk * 32);
            mma16f(o[2 * nn2],     pa[kk][0], pa[kk][1], pa[kk][2], pa[kk][3], v0, v1);
            mma16f(o[2 * nn2 + 1], pa[kk][0], pa[kk][1], pa[kk][2], pa[kk][3], v2, v3);
        }
    }

#pragma unroll
    for (int off = 1; off <= 2; off <<= 1) {
        l_lo += __shfl_xor_sync(0xffffffffu, l_lo, off);
        l_hi += __shfl_xor_sync(0xffffffffu, l_hi, off);
    }
    float inv_lo, inv_hi;
    asm("rcp.approx.f32 %0, %1;" : "=f"(inv_lo) : "f"(l_lo));
    asm("rcp.approx.f32 %0, %1;" : "=f"(inv_hi) : "f"(l_hi));
    __syncthreads();
#pragma unroll
    for (int nn = 0; nn < 8; nn++) {
        int d0 = nn * 8 + 2 * t;
        st[(d0)     * 132 + i0w + g]     = f2tf32f(o[nn][0] * inv_lo);
        st[(d0 + 1) * 132 + i0w + g]     = f2tf32f(o[nn][1] * inv_lo);
        st[(d0)     * 132 + i0w + g + 8] = f2tf32f(o[nn][2] * inv_hi);
        st[(d0 + 1) * 132 + i0w + g + 8] = f2tf32f(o[nn][3] * inv_hi);
    }
    __syncthreads();

    float* ob = out + ((size_t)(b * 256 + h * 64)) * 4096 + qt * 128;
#pragma unroll
    for (int p = 0; p < 8; p++) {
        int idx = tid + p * 256;
        int d = idx >> 5, i4 = (idx & 31) * 4;
        *(float4*)(ob + (size_t)d * 4096 + i4) = *(const float4*)(st + d * 132 + i4);
    }
}

// ---------------------------------------------------------------------------
extern "C" void kernel_launch(void* const* d_in, const int* in_sizes, int n_in,
                              void* d_out, int out_size) {
    const float* x        = (const float*)d_in[0];
    const float* gn_scale = (const float*)d_in[1];
    const float* gn_bias  = (const float*)d_in[2];
    const float* w_qkv    = (const float*)d_in[3];
    const float* w_proj   = (const float*)d_in[4];
    const float* b_proj   = (const float*)d_in[5];
    float* out = (float*)d_out;

    float *hn, *att, *wq, *wp;
    unsigned *qbf, *kbf, *vbf;
    cudaGetSymbolAddress((void**)&hn,  g_hn);
    cudaGetSymbolAddress((void**)&att, g_att);
    cudaGetSymbolAddress((void**)&wq,  g_wq);
    cudaGetSymbolAddress((void**)&wp,  g_wp);
    cudaGetSymbolAddress((void**)&qbf, g_qbf);
    cudaGetSymbolAddress((void**)&kbf, g_kbf);
    cudaGetSymbolAddress((void**)&vbf, g_vbf);

    // 0) pre-round weights to tf32 (rna)
    round_w<<<768, 256>>>(w_qkv, w_proj, wq, wp);

    // 1) GroupNorm (register-cached, tf32-rounded output)
    gn_kernel<<<64, 1024>>>(x, gn_scale, gn_bias, hn);

    // 2) QKV projection (cp.async pipeline), epilogue emits f16x2 layouts
    cudaFuncSetAttribute(gemm_mma<768, false, true>,
                         cudaFuncAttributeMaxDynamicSharedMemorySize, GEMM_SMEM_BYTES);
    gemm_mma<768, false, true><<<dim3(32, 12, 2), 256, GEMM_SMEM_BYTES>>>(
        wq, hn, nullptr, nullptr, nullptr, qbf, kbf, vbf);

    // 3) Flash attention (f16-D S, deferred PV) — R13 verbatim
    cudaFuncSetAttribute(attn_kernel, cudaFuncAttributeMaxDynamicSharedMemorySize, ATTN_SMEM_BYTES);
    attn_kernel<<<dim3(32, 4, 2), 256, ATTN_SMEM_BYTES>>>(qbf, kbf, vbf, att);

    // 4) Output projection + bias + residual
    cudaFuncSetAttribute(gemm_mma<256, true, false>,
                         cudaFuncAttributeMaxDynamicSharedMemorySize, GEMM_SMEM_BYTES);
    gemm_mma<256, true, false><<<dim3(32, 4, 2), 256, GEMM_SMEM_BYTES>>>(
        wp, att, out, b_proj, x, nullptr, nullptr, nullptr);
}

// round 16
// speedup vs baseline: 1.4495x; 1.0436x over previous
#include <cuda_runtime.h>
#include <cstddef>

// Scratch (allocation-free rule: device globals)
__device__ float    g_hn [2u * 256u * 4096u];   // groupnorm output (tf32-rounded)
__device__ float    g_att[2u * 256u * 4096u];   // attention output (tf32-rounded)
__device__ float    g_wq [768u * 256u];         // w_qkv tf32-rounded
__device__ float    g_wp [256u * 256u];         // w_proj tf32-rounded
__device__ unsigned g_qbf[2u * 4u * 4096u * 32u];  // Q f16x2 [b,h][token][d/2] (pre-scaled)
__device__ unsigned g_kbf[2u * 4u * 4096u * 32u];  // K f16x2 [b,h][token][d/2]
__device__ unsigned g_vbf[2u * 4u * 64u * 2048u];  // V f16x2 [b,h][d][token/2]

// ---------------------------------------------------------------------------
// helpers
// ---------------------------------------------------------------------------
__device__ __forceinline__ unsigned f2tf32(float x) {
    unsigned u; asm("cvt.rna.tf32.f32 %0, %1;" : "=r"(u) : "f"(x)); return u;
}
__device__ __forceinline__ float f2tf32f(float x) { return __uint_as_float(f2tf32(x)); }
__device__ __forceinline__ unsigned packf16(float lo, float hi) {
    unsigned d; asm("cvt.rn.f16x2.f32 %0, %1, %2;" : "=r"(d) : "f"(hi), "f"(lo)); return d;
}
__device__ __forceinline__ unsigned ex2x2(unsigned x) {
    unsigned r; asm("ex2.approx.f16x2 %0, %1;" : "=r"(r) : "r"(x)); return r;
}
__device__ __forceinline__ unsigned hadd2(unsigned a, unsigned b) {
    unsigned r; asm("add.rn.f16x2 %0, %1, %2;" : "=r"(r) : "r"(a), "r"(b)); return r;
}
__device__ __forceinline__ float h2sum(unsigned v) {
    float a, b;
    asm("{\n\t.reg .f16 l, h;\n\tmov.b32 {l, h}, %2;\n\t"
        "cvt.f32.f16 %0, l;\n\tcvt.f32.f16 %1, h;\n\t}"
        : "=f"(a), "=f"(b) : "r"(v));
    return a + b;
}
__device__ __forceinline__ void mma8(float* c, unsigned a0, unsigned a1, unsigned a2, unsigned a3,
                                     unsigned b0, unsigned b1) {
    asm volatile("mma.sync.aligned.m16n8k8.row.col.f32.tf32.tf32.f32 "
                 "{%0,%1,%2,%3}, {%4,%5,%6,%7}, {%8,%9}, {%0,%1,%2,%3};"
                 : "+f"(c[0]), "+f"(c[1]), "+f"(c[2]), "+f"(c[3])
                 : "r"(a0), "r"(a1), "r"(a2), "r"(a3), "r"(b0), "r"(b1));
}
__device__ __forceinline__ void mma16f(float* c, unsigned a0, unsigned a1, unsigned a2, unsigned a3,
                                       unsigned b0, unsigned b1) {
    asm volatile("mma.sync.aligned.m16n8k16.row.col.f32.f16.f16.f32 "
                 "{%0,%1,%2,%3}, {%4,%5,%6,%7}, {%8,%9}, {%0,%1,%2,%3};"
                 : "+f"(c[0]), "+f"(c[1]), "+f"(c[2]), "+f"(c[3])
                 : "r"(a0), "r"(a1), "r"(a2), "r"(a3), "r"(b0), "r"(b1));
}
__device__ __forceinline__ void mma16h(unsigned* c, unsigned a0, unsigned a1, unsigned a2,
                                       unsigned a3, unsigned b0, unsigned b1) {
    asm volatile("mma.sync.aligned.m16n8k16.row.col.f16.f16.f16.f16 "
                 "{%0,%1}, {%2,%3,%4,%5}, {%6,%7}, {%0,%1};"
                 : "+r"(c[0]), "+r"(c[1])
                 : "r"(a0), "r"(a1), "r"(a2), "r"(a3), "r"(b0), "r"(b1));
}
__device__ __forceinline__ void cpasync16(unsigned dst, const void* src) {
    asm volatile("cp.async.cg.shared.global [%0], [%1], 16;" :: "r"(dst), "l"(src));
}
__device__ __forceinline__ void ldsm4(unsigned& r0, unsigned& r1, unsigned& r2, unsigned& r3,
                                      unsigned addr) {
    asm volatile("ldmatrix.sync.aligned.m8n8.x4.shared.b16 {%0,%1,%2,%3}, [%4];"
                 : "=r"(r0), "=r"(r1), "=r"(r2), "=r"(r3) : "r"(addr));
}

// ---------------------------------------------------------------------------
// One-shot: round weights to tf32 (rna).
// ---------------------------------------------------------------------------
__global__ void __launch_bounds__(256) round_w(const float* __restrict__ wq,
                                               const float* __restrict__ wp,
                                               float* __restrict__ oq,
                                               float* __restrict__ op) {
    int i = blockIdx.x * 256 + threadIdx.x;
    oq[i] = f2tf32f(wq[i]);
    if (i < 256 * 256) op[i] = f2tf32f(wp[i]);
}

// ---------------------------------------------------------------------------
// GroupNorm, register-cached single-pass (R15, known good).
// ---------------------------------------------------------------------------
__global__ void __launch_bounds__(1024) gn_kernel(const float* __restrict__ x,
                                                  const float* __restrict__ scale,
                                                  const float* __restrict__ bias,
                                                  float* __restrict__ out) {
    const int b = blockIdx.x >> 5;
    const int g = blockIdx.x & 31;
    const float4* xp4 = (const float4*)(x   + ((size_t)b * 256 + g * 8) * 4096);
    float4*       op4 = (float4*)      (out + ((size_t)b * 256 + g * 8) * 4096);
    const int tid = threadIdx.x;

    float4 v[8];
    float s = 0.f, s2 = 0.f;
#pragma unroll
    for (int k = 0; k < 8; k++) {
        v[k] = xp4[tid + k * 1024];
        s  += (v[k].x + v[k].y) + (v[k].z + v[k].w);
        s2 += (v[k].x * v[k].x + v[k].y * v[k].y) + (v[k].z * v[k].z + v[k].w * v[k].w);
    }
#pragma unroll
    for (int off = 16; off >= 1; off >>= 1) {
        s  += __shfl_xor_sync(0xffffffffu, s,  off);
        s2 += __shfl_xor_sync(0xffffffffu, s2, off);
    }
    __shared__ float rs[32], rs2[32], bc[2];
    if ((tid & 31) == 0) { rs[tid >> 5] = s; rs2[tid >> 5] = s2; }
    __syncthreads();
    if (tid < 32) {
        float a = rs[tid], a2 = rs2[tid];
#pragma unroll
        for (int off = 16; off >= 1; off >>= 1) {
            a  += __shfl_xor_sync(0xffffffffu, a,  off);
            a2 += __shfl_xor_sync(0xffffffffu, a2, off);
        }
        if (tid == 0) { bc[0] = a; bc[1] = a2; }
    }
    __syncthreads();
    const float mean = bc[0] * (1.f / 32768.f);
    const float var  = bc[1] * (1.f / 32768.f) - mean * mean;
    const float inv  = rsqrtf(var + 1e-5f);

#pragma unroll
    for (int k = 0; k < 8; k++) {
        const int c = g * 8 + k;
        const float a  = inv * scale[c];
        const float b2 = bias[c] - mean * a;
        float4 o;
        o.x = f2tf32f(v[k].x * a + b2);
        o.y = f2tf32f(v[k].y * a + b2);
        o.z = f2tf32f(v[k].z * a + b2);
        o.w = f2tf32f(v[k].w * a + b2);
        op4[tid + k * 1024] = o;
    }
}

// ---------------------------------------------------------------------------
// tf32 GEMM, cp.async double-buffered (R13/R15, known good).
// ---------------------------------------------------------------------------
#define GEMM_SMEM_BYTES ((2 * 64 * 36 + 2 * 32 * 136) * 4)

template <int MT, bool EPI, bool QKVOUT>
__global__ void __launch_bounds__(256) gemm_mma(const float* __restrict__ A,
                                                const float* __restrict__ Bmat,
                                                float* __restrict__ C,
                                                const float* __restrict__ bias,
                                                const float* __restrict__ resid,
                                                unsigned* __restrict__ qbf,
                                                unsigned* __restrict__ kbf,
                                                unsigned* __restrict__ vbf) {
    const int K = 256, N = 4096;
    extern __shared__ float dsm[];
    const unsigned as_a = (unsigned)__cvta_generic_to_shared(dsm);
    const unsigned bs_a = as_a + 2 * 64 * 36 * 4;

    const int bn = blockIdx.x * 128, bm = blockIdx.y * 64, b = blockIdx.z;
    const float* Bb = Bmat + (size_t)b * K * N;

    const int tid = threadIdx.x;
    const int w = tid >> 5, lane = tid & 31, g = lane >> 2, t = lane & 3;
    const int wm = (w >> 1) * 16, wn = (w & 1) * 64;

#define G_ISSUE(st, d)                                                                 \
    {                                                                                  \
        _Pragma("unroll")                                                              \
        for (int p = 0; p < 2; p++) {                                                  \
            int idx = tid + p * 256;                                                   \
            int m = idx >> 3, kq = (idx & 7) * 4;                                      \
            cpasync16(as_a + ((d) * 2304 + m * 36 + kq) * 4,                           \
                      A + (size_t)(bm + m) * K + (st) * 32 + kq);                      \
        }                                                                              \
        _Pragma("unroll")                                                              \
        for (int p = 0; p < 4; p++) {                                                  \
            int idx = tid + p * 256;                                                   \
            int k = idx >> 5, nq = (idx & 31) * 4;                                     \
            cpasync16(bs_a + ((d) * 4352 + k * 136 + nq) * 4,                          \
                      Bb + (size_t)((st) * 32 + k) * N + bn + nq);                     \
        }                                                                              \
        asm volatile("cp.async.commit_group;");                                        \
    }

    float acc[8][4];
#pragma unroll
    for (int nn = 0; nn < 8; nn++)
#pragma unroll
        for (int e = 0; e < 4; e++) acc[nn][e] = 0.f;

    G_ISSUE(0, 0);

    for (int kc = 0; kc < 8; kc++) {
        asm volatile("cp.async.wait_group 0;");
        __syncthreads();
        if (kc < 7) G_ISSUE(kc + 1, (kc + 1) & 1);

        const float* as = dsm + (kc & 1) * 2304;
        const float* bs = dsm + 2 * 2304 + (kc & 1) * 4352;
#pragma unroll
        for (int kk = 0; kk < 4; kk++) {
            unsigned a0 = __float_as_uint(as[(wm + g)     * 36 + kk * 8 + t]);
            unsigned a1 = __float_as_uint(as[(wm + g + 8) * 36 + kk * 8 + t]);
            unsigned a2 = __float_as_uint(as[(wm + g)     * 36 + kk * 8 + t + 4]);
            unsigned a3 = __float_as_uint(as[(wm + g + 8) * 36 + kk * 8 + t + 4]);
#pragma unroll
            for (int nn = 0; nn < 8; nn++) {
                unsigned b0 = __float_as_uint(bs[(kk * 8 + t)     * 136 + wn + nn * 8 + g]);
                unsigned b1 = __float_as_uint(bs[(kk * 8 + t + 4) * 136 + wn + nn * 8 + g]);
                mma8(acc[nn], a0, a1, a2, a3, b0, b1);
            }
        }
    }

    if (QKVOUT) {
        const int sel = blockIdx.y >> 2, hh = blockIdx.y & 3;
        if (sel < 2) {
            const float scl = (sel == 0) ? 0.125f * 1.4426950408889634f : 1.f;
            unsigned* outp = (sel == 0 ? qbf : kbf) + ((size_t)(b * 4 + hh) * 4096) * 32;
#pragma unroll
            for (int nn = 0; nn < 8; nn++) {
                float p0 = __shfl_xor_sync(0xffffffffu, acc[nn][0], 4);
                float p1 = __shfl_xor_sync(0xffffffffu, acc[nn][1], 4);
                float p2 = __shfl_xor_sync(0xffffffffu, acc[nn][2], 4);
                float p3 = __shfl_xor_sync(0xffffffffu, acc[nn][3], 4);
                if (!(g & 1)) {
                    int tok = bn + wn + nn * 8 + 2 * t;
                    int dpl = (wm + g) >> 1, dph = dpl + 4;
                    outp[(size_t)tok * 32 + dpl]       = packf16(acc[nn][0] * scl, p0 * scl);
                    outp[(size_t)(tok + 1) * 32 + dpl] = packf16(acc[nn][1] * scl, p1 * scl);
                    outp[(size_t)tok * 32 + dph]       = packf16(acc[nn][2] * scl, p2 * scl);
                    outp[(size_t)(tok + 1) * 32 + dph] = packf16(acc[nn][3] * scl, p3 * scl);
                }
            }
        } else {
            unsigned* outp = vbf + (size_t)(b * 4 + hh) * 64 * 2048;
#pragma unroll
            for (int nn = 0; nn < 8; nn++) {
                int tokp = (bn + wn + nn * 8) / 2 + t;
                outp[(size_t)(wm + g) * 2048 + tokp]     = packf16(acc[nn][0], acc[nn][1]);
                outp[(size_t)(wm + g + 8) * 2048 + tokp] = packf16(acc[nn][2], acc[nn][3]);
            }
        }
        return;
    }

    float* Cb = C + (size_t)b * MT * N;
    const int m0 = bm + wm + g;
#pragma unroll
    for (int nn = 0; nn < 8; nn++) {
        int col = bn + wn + nn * 8 + 2 * t;
        float2 v0 = make_float2(acc[nn][0], acc[nn][1]);
        float2 v1 = make_float2(acc[nn][2], acc[nn][3]);
        if (EPI) {
            float bz0 = bias[m0], bz1 = bias[m0 + 8];
            const float* rb2 = resid + (size_t)b * MT * N;
            float2 r0 = *(const float2*)(rb2 + (size_t)m0 * N + col);
            float2 r1 = *(const float2*)(rb2 + (size_t)(m0 + 8) * N + col);
            v0.x += bz0 + r0.x; v0.y += bz0 + r0.y;
            v1.x += bz1 + r1.x; v1.y += bz1 + r1.y;
        }
        *(float2*)(Cb + (size_t)m0 * N + col) = v0;
        *(float2*)(Cb + (size_t)(m0 + 8) * N + col) = v1;
    }
}

// ---------------------------------------------------------------------------
// Flash attention, WIDE WARP TILES: 128 threads = 4 warps x 32 q-rows.
// Each warp's two 16-row groups SHARE the K/V fragment loads (B operands are
// row-group independent) -> smem traffic x0.56 vs 16-row warps.
// f16-D S mma, deferred PV, two 64-key tiles per barrier region,
// K ring 2 pairs, V ring 3 pairs. launch_bounds(128,2): reg cap 255.
// ---------------------------------------------------------------------------
#define KV_STRIDE 36
#define KV_BUF    (64 * KV_STRIDE)
#define PAIR_BUF  (2 * KV_BUF)
#define ATTN_SMEM_BYTES ((128 * KV_STRIDE + 5 * PAIR_BUF) * 4)   // 110592

__global__ void __launch_bounds__(128, 2) attn_kernel(const unsigned* __restrict__ qbf,
                                                      const unsigned* __restrict__ kbf,
                                                      const unsigned* __restrict__ vbf,
                                                      float* __restrict__ out) {
    extern __shared__ char smraw[];
    float* st = (float*)smraw;                    // [64][132] output staging (reuse)
    const unsigned sm_u32 = (unsigned)__cvta_generic_to_shared(smraw);
    const unsigned qs_a = sm_u32;
    const unsigned ks_a = sm_u32 + 128 * KV_STRIDE * 4;
    const unsigned vs_a = ks_a + 2 * PAIR_BUF * 4;

    const int b = blockIdx.z, h = blockIdx.y, qt = blockIdx.x;
    const unsigned* qb = qbf + ((size_t)(b * 4 + h) * 4096 + qt * 128) * 32;
    const unsigned* kb = kbf + ((size_t)(b * 4 + h) * 4096) * 32;
    const unsigned* vb = vbf + (size_t)(b * 4 + h) * 64 * 2048;

    const int tid = threadIdx.x;
    const int lane = tid & 31, g = lane >> 2, t = lane & 3;
    const int w = tid >> 5;
    const int i0 = w * 32;                         // warp's first q-row (32 rows)

    const unsigned qoff0 = (((unsigned)(i0 +      (lane & 15)) * KV_STRIDE) << 2) + ((lane >> 4) << 4);
    const unsigned qoff1 = (((unsigned)(i0 + 16 + (lane & 15)) * KV_STRIDE) << 2) + ((lane >> 4) << 4);
    const unsigned koff  = ((((lane & 7) + ((lane & 16) >> 1)) * KV_STRIDE) << 2) + ((lane & 8) << 1);

    // ---- Q loads join cp.async group 0 (128 rows x 8 chunks, 128 threads) ----
#pragma unroll
    for (int p = 0; p < 8; p++) {
        int idx = tid + p * 128;
        int i = idx >> 3, c = idx & 7;
        cpasync16(qs_a + (i * KV_STRIDE + c * 4) * 4, qb + (size_t)i * 32 + c * 4);
    }

#define ISSUE_PAIR(kp, kbuf, vbuf)                                                   \
    {                                                                                \
        _Pragma("unroll")                                                            \
        for (int p = 0; p < 8; p++) {                                                \
            int idx = tid + p * 128;                                                 \
            int r = idx >> 3, c = idx & 7;                                           \
            cpasync16(ks_a + ((kbuf) * PAIR_BUF + r * KV_STRIDE + c * 4) * 4,        \
                      kb + ((size_t)((kp) * 128 + r)) * 32 + c * 4);                 \
        }                                                                            \
        _Pragma("unroll")                                                            \
        for (int p = 0; p < 8; p++) {                                                \
            int idx = tid + p * 128;                                                 \
            int half = idx >> 9, r = (idx >> 3) & 63, c = idx & 7;                   \
            cpasync16(vs_a + ((vbuf) * PAIR_BUF + half * KV_BUF + r * KV_STRIDE + c * 4) * 4, \
                      vb + (size_t)r * 2048 + ((kp) * 2 + half) * 32 + c * 4);       \
        }                                                                            \
        asm volatile("cp.async.commit_group;");                                      \
    }

    ISSUE_PAIR(0, 0, 0);

    float o[2][8][4];
    float l_lo[2] = {0.f, 0.f}, l_hi[2] = {0.f, 0.f};
#pragma unroll
    for (int rg = 0; rg < 2; rg++)
#pragma unroll
        for (int nn = 0; nn < 8; nn++)
#pragma unroll
            for (int e = 0; e < 4; e++) o[rg][nn][e] = 0.f;

    unsigned pa[2][4][4];          // deferred P frags, both row groups
    unsigned vprev = 0;

    for (int kp = 0; kp < 32; kp++) {
        asm volatile("cp.async.wait_group 0;");
        __syncthreads();
        if (kp < 31) ISSUE_PAIR(kp + 1, (kp + 1) & 1, (kp + 1) % 3);

        const unsigned kpb = ks_a + (kp & 1) * PAIR_BUF * 4;
        const unsigned vpb = vs_a + (kp % 3) * PAIR_BUF * 4;

#pragma unroll
        for (int hf = 0; hf < 2; hf++) {
            const unsigned ksb_a = kpb + hf * KV_BUF * 4;

            // ---- S(n), both row groups, K frags loaded ONCE ----
            unsigned s16[2][8][2];
#pragma unroll
            for (int rg = 0; rg < 2; rg++)
#pragma unroll
                for (int nn = 0; nn < 8; nn++) { s16[rg][nn][0] = 0u; s16[rg][nn][1] = 0u; }
#pragma unroll
            for (int kk = 0; kk < 4; kk++) {
                unsigned a00, a01, a02, a03, a10, a11, a12, a13;
                ldsm4(a00, a01, a02, a03, qs_a + qoff0 + kk * 32);
                ldsm4(a10, a11, a12, a13, qs_a + qoff1 + kk * 32);
#pragma unroll
                for (int nn2 = 0; nn2 < 4; nn2++) {
                    unsigned k0, k1, k2, k3;
                    ldsm4(k0, k1, k2, k3, ksb_a + koff + nn2 * (16 * KV_STRIDE * 4) + kk * 32);
                    mma16h(s16[0][2 * nn2],     a00, a01, a02, a03, k0, k1);
                    mma16h(s16[0][2 * nn2 + 1], a00, a01, a02, a03, k2, k3);
                    mma16h(s16[1][2 * nn2],     a10, a11, a12, a13, k0, k1);
                    mma16h(s16[1][2 * nn2 + 1], a10, a11, a12, a13, k2, k3);
                }
            }

            // ---- deferred PV(n-1), both row groups, V frags loaded ONCE ----
            if (kp > 0 || hf > 0) {
#pragma unroll
                for (int kk = 0; kk < 4; kk++) {
#pragma unroll
                    for (int nn2 = 0; nn2 < 4; nn2++) {
                        unsigned v0, v1, v2, v3;
                        ldsm4(v0, v1, v2, v3, vprev + koff + nn2 * (16 * KV_STRIDE * 4) + kk * 32);
                        mma16f(o[0][2 * nn2],     pa[0][kk][0], pa[0][kk][1], pa[0][kk][2], pa[0][kk][3], v0, v1);
                        mma16f(o[0][2 * nn2 + 1], pa[0][kk][0], pa[0][kk][1], pa[0][kk][2], pa[0][kk][3], v2, v3);
                        mma16f(o[1][2 * nn2],     pa[1][kk][0], pa[1][kk][1], pa[1][kk][2], pa[1][kk][3], v0, v1);
                        mma16f(o[1][2 * nn2 + 1], pa[1][kk][0], pa[1][kk][1], pa[1][kk][2], pa[1][kk][3], v2, v3);
                    }
                }
            }

            // ---- softmax(n) both row groups: pa = ex2x2(s16) ----
#pragma unroll
            for (int rg = 0; rg < 2; rg++) {
#pragma unroll
                for (int kk = 0; kk < 4; kk++) {
                    pa[rg][kk][0] = ex2x2(s16[rg][2 * kk][0]);
                    pa[rg][kk][1] = ex2x2(s16[rg][2 * kk][1]);
                    pa[rg][kk][2] = ex2x2(s16[rg][2 * kk + 1][0]);
                    pa[rg][kk][3] = ex2x2(s16[rg][2 * kk + 1][1]);
                }
                unsigned sg = hadd2(hadd2(hadd2(pa[rg][0][0], pa[rg][0][2]), hadd2(pa[rg][1][0], pa[rg][1][2])),
                                    hadd2(hadd2(pa[rg][2][0], pa[rg][2][2]), hadd2(pa[rg][3][0], pa[rg][3][2])));
                unsigned sh = hadd2(hadd2(hadd2(pa[rg][0][1], pa[rg][0][3]), hadd2(pa[rg][1][1], pa[rg][1][3])),
                                    hadd2(hadd2(pa[rg][2][1], pa[rg][2][3]), hadd2(pa[rg][3][1], pa[rg][3][3])));
                l_lo[rg] += h2sum(sg);
                l_hi[rg] += h2sum(sh);
            }

            vprev = vpb + hf * KV_BUF * 4;
        }
    }

    // ---- final deferred PV (tile 63) ----
#pragma unroll
    for (int kk = 0; kk < 4; kk++) {
#pragma unroll
        for (int nn2 = 0; nn2 < 4; nn2++) {
            unsigned v0, v1, v2, v3;
            ldsm4(v0, v1, v2, v3, vprev + koff + nn2 * (16 * KV_STRIDE * 4) + kk * 32);
            mma16f(o[0][2 * nn2],     pa[0][kk][0], pa[0][kk][1], pa[0][kk][2], pa[0][kk][3], v0, v1);
            mma16f(o[0][2 * nn2 + 1], pa[0][kk][0], pa[0][kk][1], pa[0][kk][2], pa[0][kk][3], v2, v3);
            mma16f(o[1][2 * nn2],     pa[1][kk][0], pa[1][kk][1], pa[1][kk][2], pa[1][kk][3], v0, v1);
            mma16f(o[1][2 * nn2 + 1], pa[1][kk][0], pa[1][kk][1], pa[1][kk][2], pa[1][kk][3], v2, v3);
        }
    }

    // ---- quad-reduce l, normalize, stage, store (tf32-rounded) ----
    float inv_lo[2], inv_hi[2];
#pragma unroll
    for (int rg = 0; rg < 2; rg++) {
#pragma unroll
        for (int off = 1; off <= 2; off <<= 1) {
            l_lo[rg] += __shfl_xor_sync(0xffffffffu, l_lo[rg], off);
            l_hi[rg] += __shfl_xor_sync(0xffffffffu, l_hi[rg], off);
        }
        asm("rcp.approx.f32 %0, %1;" : "=f"(inv_lo[rg]) : "f"(l_lo[rg]));
        asm("rcp.approx.f32 %0, %1;" : "=f"(inv_hi[rg]) : "f"(l_hi[rg]));
    }
    __syncthreads();   // working smem dead; reuse as staging
#pragma unroll
    for (int rg = 0; rg < 2; rg++) {
        int iw = i0 + rg * 16;
#pragma unroll
        for (int nn = 0; nn < 8; nn++) {
            int d0 = nn * 8 + 2 * t;
            st[(d0)     * 132 + iw + g]     = f2tf32f(o[rg][nn][0] * inv_lo[rg]);
            st[(d0 + 1) * 132 + iw + g]     = f2tf32f(o[rg][nn][1] * inv_lo[rg]);
            st[(d0)     * 132 + iw + g + 8] = f2tf32f(o[rg][nn][2] * inv_hi[rg]);
            st[(d0 + 1) * 132 + iw + g + 8] = f2tf32f(o[rg][nn][3] * inv_hi[rg]);
        }
    }
    __syncthreads();

    float* ob = out + ((size_t)(b * 256 + h * 64)) * 4096 + qt * 128;
#pragma unroll
    for (int p = 0; p < 16; p++) {
        int idx = tid + p * 128;
        int d = idx >> 5, i4 = (idx & 31) * 4;
        *(float4*)(ob + (size_t)d * 4096 + i4) = *(const float4*)(st + d * 132 + i4);
    }
}

// ---------------------------------------------------------------------------
extern "C" void kernel_launch(void* const* d_in, const int* in_sizes, int n_in,
                              void* d_out, int out_size) {
    const float* x        = (const float*)d_in[0];
    const float* gn_scale = (const float*)d_in[1];
    const float* gn_bias  = (const float*)d_in[2];
    const float* w_qkv    = (const float*)d_in[3];
    const float* w_proj   = (const float*)d_in[4];
    const float* b_proj   = (const float*)d_in[5];
    float* out = (float*)d_out;

    float *hn, *att, *wq, *wp;
    unsigned *qbf, *kbf, *vbf;
    cudaGetSymbolAddress((void**)&hn,  g_hn);
    cudaGetSymbolAddress((void**)&att, g_att);
    cudaGetSymbolAddress((void**)&wq,  g_wq);
    cudaGetSymbolAddress((void**)&wp,  g_wp);
    cudaGetSymbolAddress((void**)&qbf, g_qbf);
    cudaGetSymbolAddress((void**)&kbf, g_kbf);
    cudaGetSymbolAddress((void**)&vbf, g_vbf);

    // 0) pre-round weights to tf32 (rna)
    round_w<<<768, 256>>>(w_qkv, w_proj, wq, wp);

    // 1) GroupNorm (register-cached, tf32-rounded output)
    gn_kernel<<<64, 1024>>>(x, gn_scale, gn_bias, hn);

    // 2) QKV projection (cp.async pipeline), epilogue emits f16x2 layouts
    cudaFuncSetAttribute(gemm_mma<768, false, true>,
                         cudaFuncAttributeMaxDynamicSharedMemorySize, GEMM_SMEM_BYTES);
    gemm_mma<768, false, true><<<dim3(32, 12, 2), 256, GEMM_SMEM_BYTES>>>(
        wq, hn, nullptr, nullptr, nullptr, qbf, kbf, vbf);

    // 3) Flash attention (wide warp tiles, shared K/V frags, deferred PV)
    cudaFuncSetAttribute(attn_kernel, cudaFuncAttributeMaxDynamicSharedMemorySize, ATTN_SMEM_BYTES);
    attn_kernel<<<dim3(32, 4, 2), 128, ATTN_SMEM_BYTES>>>(qbf, kbf, vbf, att);

    // 4) Output projection + bias + residual
    cudaFuncSetAttribute(gemm_mma<256, true, false>,
                         cudaFuncAttributeMaxDynamicSharedMemorySize, GEMM_SMEM_BYTES);
    gemm_mma<256, true, false><<<dim3(32, 4, 2), 256, GEMM_SMEM_BYTES>>>(
        wp, att, out, b_proj, x, nullptr, nullptr, nullptr);
}